// round 8
// baseline (speedup 1.0000x reference)
#include <cuda_runtime.h>
#include <cuda_bf16.h>
#include <cstdint>
#include <math.h>

#define B_  32
#define C_  512
#define HW  1024
#define EPS 1e-5f

typedef __nv_bfloat16 bf16;

// ---------------------------------------------------------------------------
// Scratch (__device__ globals; allocation-free rule)
// ---------------------------------------------------------------------------
__device__ __align__(128) bf16  g_hnT[(size_t)B_ * HW * C_];   // [b, p, c]
__device__ __align__(128) bf16  g_qT [(size_t)B_ * HW * C_];   // [b, p, c]
__device__ __align__(128) bf16  g_kT [(size_t)B_ * HW * C_];   // [b, p, c]
__device__ __align__(128) bf16  g_v  [(size_t)B_ * C_ * HW];   // [b, c, p]
__device__ __align__(128) bf16  g_oT [(size_t)B_ * HW * C_];   // [b, p, c]
__device__ __align__(128) float g_attn [(size_t)B_ * HW * HW]; // fp32 scores
__device__ __align__(128) bf16  g_probs[(size_t)B_ * HW * HW]; // bf16 probs
__device__ __align__(128) bf16  g_w[4][C_ * C_];               // wq,wk,wv,wp bf16
__device__ float2 g_stats[B_ * 32];

// ---------------------------------------------------------------------------
// Helpers
// ---------------------------------------------------------------------------
__device__ __forceinline__ uint32_t smem_u32(const void* p) {
    uint32_t a;
    asm("{ .reg .u64 t; cvta.to.shared.u64 t, %1; cvt.u32.u64 %0, t; }" : "=r"(a) : "l"(p));
    return a;
}
__device__ __forceinline__ void cp16(uint32_t s, const void* g) {
    asm volatile("cp.async.cg.shared.global [%0], [%1], 16;" :: "r"(s), "l"(g));
}
__device__ __forceinline__ void ldsm4(uint32_t* r, uint32_t a) {
    asm volatile("ldmatrix.sync.aligned.m8n8.x4.shared.b16 {%0,%1,%2,%3}, [%4];"
                 : "=r"(r[0]), "=r"(r[1]), "=r"(r[2]), "=r"(r[3]) : "r"(a));
}
__device__ __forceinline__ void mma16(float* d, const uint32_t* a, uint32_t b0, uint32_t b1) {
    asm volatile("mma.sync.aligned.m16n8k16.row.col.f32.bf16.bf16.f32 "
        "{%0,%1,%2,%3}, {%4,%5,%6,%7}, {%8,%9}, {%0,%1,%2,%3};"
        : "+f"(d[0]), "+f"(d[1]), "+f"(d[2]), "+f"(d[3])
        : "r"(a[0]), "r"(a[1]), "r"(a[2]), "r"(a[3]), "r"(b0), "r"(b1));
}

// ---------------------------------------------------------------------------
// Weight fp32 -> bf16 conversion, all four weights in one launch
// ---------------------------------------------------------------------------
__global__ __launch_bounds__(256) void cvt4_kernel(
    const float* __restrict__ w0, const float* __restrict__ w1,
    const float* __restrict__ w2, const float* __restrict__ w3,
    bf16* __restrict__ dst)
{
    const float* src = (blockIdx.y == 0) ? w0 : (blockIdx.y == 1) ? w1
                     : (blockIdx.y == 2) ? w2 : w3;
    bf16* d = dst + (size_t)blockIdx.y * C_ * C_;
    int i = blockIdx.x * 256 + threadIdx.x;
    float4 v = *(const float4*)(src + i * 4);
    __nv_bfloat162* d2 = (__nv_bfloat162*)(d + i * 4);
    d2[0] = __floats2bfloat162_rn(v.x, v.y);
    d2[1] = __floats2bfloat162_rn(v.z, v.w);
}

// ---------------------------------------------------------------------------
// GroupNorm pass 1: stats per (batch, group)
// ---------------------------------------------------------------------------
__global__ __launch_bounds__(256) void gn_stats_kernel(const float* __restrict__ x,
                                                       float2* __restrict__ stats)
{
    int b = blockIdx.x >> 5, g = blockIdx.x & 31;
    const int n = 16 * HW;
    size_t base = ((size_t)b * C_ + (size_t)g * 16) * HW;
    const float4* x4 = (const float4*)(x + base);
    float s = 0.f, ss = 0.f;
    for (int i = threadIdx.x; i < n / 4; i += 256) {
        float4 v = x4[i];
        s  += v.x + v.y + v.z + v.w;
        ss += v.x * v.x + v.y * v.y + v.z * v.z + v.w * v.w;
    }
    __shared__ float sh_s[256], sh_ss[256];
    sh_s[threadIdx.x] = s; sh_ss[threadIdx.x] = ss;
    __syncthreads();
    for (int off = 128; off > 0; off >>= 1) {
        if (threadIdx.x < off) {
            sh_s[threadIdx.x]  += sh_s[threadIdx.x + off];
            sh_ss[threadIdx.x] += sh_ss[threadIdx.x + off];
        }
        __syncthreads();
    }
    if (threadIdx.x == 0) {
        float mean = sh_s[0] * (1.f / n);
        float var  = sh_ss[0] * (1.f / n) - mean * mean;
        stats[blockIdx.x] = make_float2(mean, rsqrtf(var + EPS));
    }
}

// ---------------------------------------------------------------------------
// GroupNorm pass 2: normalize + transpose -> hnT[b, p, c] (bf16)
// ---------------------------------------------------------------------------
__global__ __launch_bounds__(256) void gn_transpose_kernel(
    const float* __restrict__ x, const float* __restrict__ scale,
    const float* __restrict__ bias, const float2* __restrict__ stats,
    bf16* __restrict__ hnT)
{
    __shared__ float tile[32][33];
    int b = blockIdx.z, c0 = blockIdx.y * 32, p0 = blockIdx.x * 32;
    int lane = threadIdx.x & 31, r = threadIdx.x >> 5;
    #pragma unroll
    for (int i = 0; i < 4; i++) {
        int cl = r + i * 8, ch = c0 + cl;
        float2 st = stats[b * 32 + (ch >> 4)];
        float a = scale[ch] * st.y;
        float ad = bias[ch] - st.x * a;
        tile[cl][lane] = x[((size_t)b * C_ + ch) * HW + p0 + lane] * a + ad;
    }
    __syncthreads();
    #pragma unroll
    for (int i = 0; i < 4; i++) {
        int pl = r + i * 8;
        hnT[((size_t)b * HW + p0 + pl) * C_ + c0 + lane] = __float2bfloat16(tile[lane][pl]);
    }
}

// ---------------------------------------------------------------------------
// bf16 mma.sync GEMM: D[m,n] = alpha * sum_k A[m,k]*B[n,k]  (+bias) (+R)
// CTA tile 128x128x64, 128 threads (4 warps, 2x2), warp tile 64x64.
// 3-stage cp.async ring (sync every 64-k tile), 4-slab fragment ring.
// ---------------------------------------------------------------------------
#define BM 128
#define BN 128
#define BKB 64                          // k per tile (bf16 elems)
#define ROWB 144                        // bytes per smem row (128 data + 16 pad)
#define OSTAGE (BM * ROWB)              // 18432 bytes per operand stage
#define NSTAGE 3
#define GEMM_SMEM (2 * NSTAGE * OSTAGE) // 110592 bytes

template<bool BIAS_M, bool BIAS_N, bool RES, bool OUTBF>
__global__ __launch_bounds__(128, 2) void gemm_bf(
    const bf16* __restrict__ A, const bf16* __restrict__ Bm, void* __restrict__ Cp,
    const float* __restrict__ bias, const float* __restrict__ R,
    int M, int N, int K, size_t sA, size_t sB, size_t sC, size_t sR, float alpha)
{
    extern __shared__ char smem[];
    uint32_t su = smem_u32(smem);
    const uint32_t BOFF = NSTAGE * OSTAGE;

    int tid = threadIdx.x, lane = tid & 31, wid = tid >> 5;
    int bz = blockIdx.z;
    A += sA * bz; Bm += sB * bz;
    if (RES) R += sR * bz;
    int m0 = blockIdx.y * BM, n0 = blockIdx.x * BN;

    int wm = (wid & 1) * 64;           // warp m-offset (64-wide)
    int wn = (wid >> 1) * 64;          // warp n-offset (64-wide)
    int g = lane >> 2, c = lane & 3;

    // ldmatrix per-lane offsets (bytes, within an operand stage)
    int a_row = (lane & 7) + ((lane >> 3) & 1) * 8;
    int a_kh  = lane >> 4;
    uint32_t aoff = (uint32_t)((wm + a_row) * ROWB + a_kh * 16);
    int b_row = (lane & 7) + ((lane >> 4) & 1) * 8;
    int b_kh  = (lane >> 3) & 1;
    uint32_t boffb = (uint32_t)((wn + b_row) * ROWB + b_kh * 16);

    float acc[4][8][4];
    #pragma unroll
    for (int mt = 0; mt < 4; mt++)
        #pragma unroll
        for (int nt = 0; nt < 8; nt++)
            #pragma unroll
            for (int r_ = 0; r_ < 4; r_++) acc[mt][nt][r_] = 0.f;

    // loader: one row per thread, 8 x 16B chunks per operand per tile
    auto load_tile = [&](int kt, int st) {
        const bf16* Ag = A  + (size_t)(m0 + tid) * K + kt * BKB;
        const bf16* Bg = Bm + (size_t)(n0 + tid) * K + kt * BKB;
        uint32_t so = su + (uint32_t)st * OSTAGE + (uint32_t)tid * ROWB;
        #pragma unroll
        for (int ch = 0; ch < 8; ch++) {
            cp16(so + ch * 16,        Ag + ch * 8);
            cp16(so + BOFF + ch * 16, Bg + ch * 8);
        }
        asm volatile("cp.async.commit_group;" ::: "memory");
    };

    // fragment double buffers (one 16-k slab each)
    uint32_t af[2][4][4], bfr[2][4][4];
    auto ldsm_slab = [&](int st, int sl, int buf) {
        uint32_t abase = su + (uint32_t)st * OSTAGE + (uint32_t)sl * 32;
        uint32_t bbase = abase + BOFF;
        #pragma unroll
        for (int mt = 0; mt < 4; mt++)
            ldsm4(af[buf][mt], abase + aoff + mt * (16 * ROWB));
        #pragma unroll
        for (int pr = 0; pr < 4; pr++)
            ldsm4(bfr[buf][pr], bbase + boffb + pr * (16 * ROWB));
    };
    auto mma_slab = [&](int buf) {
        #pragma unroll
        for (int pr = 0; pr < 4; pr++)
            #pragma unroll
            for (int mt = 0; mt < 4; mt++) {
                mma16(acc[mt][pr * 2 + 0], af[buf][mt], bfr[buf][pr][0], bfr[buf][pr][1]);
                mma16(acc[mt][pr * 2 + 1], af[buf][mt], bfr[buf][pr][2], bfr[buf][pr][3]);
            }
    };

    // prologue: 2 tiles in flight
    load_tile(0, 0); load_tile(1, 1);

    const int KT = K / BKB;
    for (int kt = 0; kt < KT; kt++) {
        int st = kt % NSTAGE;
        asm volatile("cp.async.wait_group 1;" ::: "memory");   // tile kt landed
        __syncthreads();                                        // visible CTA-wide
        // 4-slab fragment ring: ld0,ld1 | mma0, ld2 | mma1, ld3 | mma2 | mma3
        ldsm_slab(st, 0, 0);
        ldsm_slab(st, 1, 1);
        mma_slab(0);
        ldsm_slab(st, 2, 0);
        if (kt + 2 < KT) load_tile(kt + 2, (kt + 2) % NSTAGE);  // stage freed last iter
        mma_slab(1);
        ldsm_slab(st, 3, 1);
        mma_slab(0);
        mma_slab(1);
    }

    // epilogue
    #pragma unroll
    for (int mt = 0; mt < 4; mt++) {
        #pragma unroll
        for (int half = 0; half < 2; half++) {
            int m = m0 + wm + mt * 16 + g + half * 8;
            float bm = BIAS_M ? bias[m] : 0.f;
            #pragma unroll
            for (int nt = 0; nt < 8; nt++) {
                int n = n0 + wn + nt * 8 + c * 2;
                float v0 = acc[mt][nt][half * 2 + 0] * alpha + bm;
                float v1 = acc[mt][nt][half * 2 + 1] * alpha + bm;
                if (BIAS_N) { v0 += bias[n]; v1 += bias[n + 1]; }
                size_t off = (size_t)m * N + n;
                if (RES) { v0 += R[off]; v1 += R[off + 1]; }
                if (OUTBF) {
                    *(__nv_bfloat162*)((bf16*)Cp + sC * bz + off) = __floats2bfloat162_rn(v0, v1);
                } else {
                    *(float2*)((float*)Cp + sC * bz + off) = make_float2(v0, v1);
                }
            }
        }
    }
}

// ---------------------------------------------------------------------------
// Row softmax: fp32 scores in -> bf16 probs out
// ---------------------------------------------------------------------------
__global__ __launch_bounds__(256) void softmax_kernel(const float* __restrict__ attn,
                                                      bf16* __restrict__ probs)
{
    size_t row = blockIdx.x;
    const float4* p4 = (const float4*)(attn + row * HW);
    int tid = threadIdx.x;
    float4 v = p4[tid];
    __shared__ float sh[256];
    float m = fmaxf(fmaxf(v.x, v.y), fmaxf(v.z, v.w));
    sh[tid] = m; __syncthreads();
    for (int off = 128; off > 0; off >>= 1) {
        if (tid < off) sh[tid] = fmaxf(sh[tid], sh[tid + off]);
        __syncthreads();
    }
    m = sh[0];
    __syncthreads();
    v.x = expf(v.x - m); v.y = expf(v.y - m);
    v.z = expf(v.z - m); v.w = expf(v.w - m);
    sh[tid] = v.x + v.y + v.z + v.w;
    __syncthreads();
    for (int off = 128; off > 0; off >>= 1) {
        if (tid < off) sh[tid] += sh[tid + off];
        __syncthreads();
    }
    float inv = 1.f / sh[0];
    __nv_bfloat162* o2 = (__nv_bfloat162*)(probs + row * HW) + tid * 2;
    o2[0] = __floats2bfloat162_rn(v.x * inv, v.y * inv);
    o2[1] = __floats2bfloat162_rn(v.z * inv, v.w * inv);
}

// ---------------------------------------------------------------------------
extern "C" void kernel_launch(void* const* d_in, const int* in_sizes, int n_in,
                              void* d_out, int out_size)
{
    const float* x  = (const float*)d_in[0];
    const float* gs = (const float*)d_in[1];
    const float* gb = (const float*)d_in[2];
    const float* wq = (const float*)d_in[3];
    const float* bq = (const float*)d_in[4];
    const float* wk = (const float*)d_in[5];
    const float* bk = (const float*)d_in[6];
    const float* wv = (const float*)d_in[7];
    const float* bv = (const float*)d_in[8];
    const float* wp = (const float*)d_in[9];
    const float* bp = (const float*)d_in[10];
    float* out = (float*)d_out;

    bf16 *hnT, *qT, *kT, *v, *oT, *probs, *wb; float* attn; float2* stats;
    cudaGetSymbolAddress((void**)&hnT,   g_hnT);
    cudaGetSymbolAddress((void**)&qT,    g_qT);
    cudaGetSymbolAddress((void**)&kT,    g_kT);
    cudaGetSymbolAddress((void**)&v,     g_v);
    cudaGetSymbolAddress((void**)&oT,    g_oT);
    cudaGetSymbolAddress((void**)&attn,  g_attn);
    cudaGetSymbolAddress((void**)&probs, g_probs);
    cudaGetSymbolAddress((void**)&wb,    g_w);
    cudaGetSymbolAddress((void**)&stats, g_stats);
    bf16 *wqb = wb, *wkb = wb + C_ * C_, *wvb = wb + 2 * C_ * C_, *wpb = wb + 3 * C_ * C_;

    cudaFuncSetAttribute(gemm_bf<false, true,  false, true >, cudaFuncAttributeMaxDynamicSharedMemorySize, GEMM_SMEM);
    cudaFuncSetAttribute(gemm_bf<true,  false, false, true >, cudaFuncAttributeMaxDynamicSharedMemorySize, GEMM_SMEM);
    cudaFuncSetAttribute(gemm_bf<false, false, false, false>, cudaFuncAttributeMaxDynamicSharedMemorySize, GEMM_SMEM);
    cudaFuncSetAttribute(gemm_bf<false, false, false, true >, cudaFuncAttributeMaxDynamicSharedMemorySize, GEMM_SMEM);
    cudaFuncSetAttribute(gemm_bf<true,  false, true,  false>, cudaFuncAttributeMaxDynamicSharedMemorySize, GEMM_SMEM);

    const size_t sCH = (size_t)C_ * HW;
    const size_t sAA = (size_t)HW * HW;
    const float  scl = 1.f / sqrtf((float)C_);

    // 0) weights -> bf16 (one launch)
    cvt4_kernel<<<dim3(C_ * C_ / 1024, 4), 256>>>(wq, wk, wv, wp, wb);

    // 1) GroupNorm stats + normalize/transpose -> hnT (bf16)
    gn_stats_kernel<<<B_ * 32, 256>>>(x, stats);
    gn_transpose_kernel<<<dim3(HW / 32, C_ / 32, B_), 256>>>(x, gs, gb, stats, hnT);

    // 2) QT/KT[p,o] = hnT @ w^T + b        (M=1024, N=512, K=512) -> bf16
    {
        dim3 g(512 / BN, 1024 / BM, B_);
        gemm_bf<false, true, false, true><<<g, 128, GEMM_SMEM>>>(
            hnT, wqb, qT, bq, nullptr, 1024, 512, 512, sCH, 0, sCH, 0, 1.f);
        gemm_bf<false, true, false, true><<<g, 128, GEMM_SMEM>>>(
            hnT, wkb, kT, bk, nullptr, 1024, 512, 512, sCH, 0, sCH, 0, 1.f);
    }
    // 3) V[co,p] = wv @ hnT^T + bv         (M=512, N=1024, K=512) -> bf16
    {
        dim3 g(1024 / BN, 512 / BM, B_);
        gemm_bf<true, false, false, true><<<g, 128, GEMM_SMEM>>>(
            wvb, hnT, v, bv, nullptr, 512, 1024, 512, 0, sCH, sCH, 0, 1.f);
    }
    // 4) S = scl * QT @ KT^T               (M=1024, N=1024, K=512) -> fp32
    {
        dim3 g(1024 / BN, 1024 / BM, B_);
        gemm_bf<false, false, false, false><<<g, 128, GEMM_SMEM>>>(
            qT, kT, attn, nullptr, nullptr, 1024, 1024, 512, sCH, sCH, sAA, 0, scl);
    }
    // 5) softmax -> bf16 probs
    softmax_kernel<<<B_ * HW, 256>>>(attn, probs);

    // 6) OT[i,co] = probs @ V^T            (M=1024, N=512, K=1024) -> bf16
    {
        dim3 g(512 / BN, 1024 / BM, B_);
        gemm_bf<false, false, false, true><<<g, 128, GEMM_SMEM>>>(
            probs, v, oT, nullptr, nullptr, 1024, 512, 1024, sAA, sCH, sCH, 0, 1.f);
    }
    // 7) out[co,p] = wp @ OT^T + bp + x    (M=512, N=1024, K=512) -> fp32 + residual
    {
        dim3 g(1024 / BN, 512 / BM, B_);
        gemm_bf<true, false, true, false><<<g, 128, GEMM_SMEM>>>(
            wpb, oT, out, bp, x, 512, 1024, 512, 0, sCH, sCH, sCH, 1.f);
    }
}

// round 9
// speedup vs baseline: 1.5247x; 1.5247x over previous
#include <cuda_runtime.h>
#include <cuda_bf16.h>
#include <cstdint>
#include <math.h>

#define B_  32
#define C_  512
#define HW  1024
#define EPS 1e-5f

typedef __nv_bfloat16 bf16;

// ---------------------------------------------------------------------------
// Scratch (__device__ globals; allocation-free rule)
// ---------------------------------------------------------------------------
__device__ __align__(128) bf16  g_hnT[(size_t)B_ * HW * C_];   // [b, p, c]
__device__ __align__(128) bf16  g_qT [(size_t)B_ * HW * C_];   // [b, p, c]
__device__ __align__(128) bf16  g_kT [(size_t)B_ * HW * C_];   // [b, p, c]
__device__ __align__(128) bf16  g_v  [(size_t)B_ * C_ * HW];   // [b, c, p]
__device__ __align__(128) bf16  g_oT [(size_t)B_ * HW * C_];   // [b, p, c]
__device__ __align__(128) float g_attn [(size_t)B_ * HW * HW]; // fp32 scores
__device__ __align__(128) bf16  g_probs[(size_t)B_ * HW * HW]; // bf16 probs
__device__ __align__(128) bf16  g_w[4][C_ * C_];               // wq,wk,wv,wp bf16
__device__ float2 g_stats[B_ * 32];

// ---------------------------------------------------------------------------
// Helpers
// ---------------------------------------------------------------------------
__device__ __forceinline__ uint32_t smem_u32(const void* p) {
    uint32_t a;
    asm("{ .reg .u64 t; cvta.to.shared.u64 t, %1; cvt.u32.u64 %0, t; }" : "=r"(a) : "l"(p));
    return a;
}
__device__ __forceinline__ void cp16(uint32_t s, const void* g) {
    asm volatile("cp.async.cg.shared.global [%0], [%1], 16;" :: "r"(s), "l"(g));
}
__device__ __forceinline__ void ldsm4(uint32_t* r, uint32_t a) {
    asm volatile("ldmatrix.sync.aligned.m8n8.x4.shared.b16 {%0,%1,%2,%3}, [%4];"
                 : "=r"(r[0]), "=r"(r[1]), "=r"(r[2]), "=r"(r[3]) : "r"(a));
}
__device__ __forceinline__ void mma16(float* d, const uint32_t* a, uint32_t b0, uint32_t b1) {
    asm volatile("mma.sync.aligned.m16n8k16.row.col.f32.bf16.bf16.f32 "
        "{%0,%1,%2,%3}, {%4,%5,%6,%7}, {%8,%9}, {%0,%1,%2,%3};"
        : "+f"(d[0]), "+f"(d[1]), "+f"(d[2]), "+f"(d[3])
        : "r"(a[0]), "r"(a[1]), "r"(a[2]), "r"(a[3]), "r"(b0), "r"(b1));
}

// ---------------------------------------------------------------------------
// Weight fp32 -> bf16 conversion, all four weights in one launch
// ---------------------------------------------------------------------------
__global__ __launch_bounds__(256) void cvt4_kernel(
    const float* __restrict__ w0, const float* __restrict__ w1,
    const float* __restrict__ w2, const float* __restrict__ w3,
    bf16* __restrict__ dst)
{
    const float* src = (blockIdx.y == 0) ? w0 : (blockIdx.y == 1) ? w1
                     : (blockIdx.y == 2) ? w2 : w3;
    bf16* d = dst + (size_t)blockIdx.y * C_ * C_;
    int i = blockIdx.x * 256 + threadIdx.x;
    float4 v = *(const float4*)(src + i * 4);
    __nv_bfloat162* d2 = (__nv_bfloat162*)(d + i * 4);
    d2[0] = __floats2bfloat162_rn(v.x, v.y);
    d2[1] = __floats2bfloat162_rn(v.z, v.w);
}

// ---------------------------------------------------------------------------
// GroupNorm pass 1: stats per (batch, group)
// ---------------------------------------------------------------------------
__global__ __launch_bounds__(256) void gn_stats_kernel(const float* __restrict__ x,
                                                       float2* __restrict__ stats)
{
    int b = blockIdx.x >> 5, g = blockIdx.x & 31;
    const int n = 16 * HW;
    size_t base = ((size_t)b * C_ + (size_t)g * 16) * HW;
    const float4* x4 = (const float4*)(x + base);
    float s = 0.f, ss = 0.f;
    for (int i = threadIdx.x; i < n / 4; i += 256) {
        float4 v = x4[i];
        s  += v.x + v.y + v.z + v.w;
        ss += v.x * v.x + v.y * v.y + v.z * v.z + v.w * v.w;
    }
    __shared__ float sh_s[256], sh_ss[256];
    sh_s[threadIdx.x] = s; sh_ss[threadIdx.x] = ss;
    __syncthreads();
    for (int off = 128; off > 0; off >>= 1) {
        if (threadIdx.x < off) {
            sh_s[threadIdx.x]  += sh_s[threadIdx.x + off];
            sh_ss[threadIdx.x] += sh_ss[threadIdx.x + off];
        }
        __syncthreads();
    }
    if (threadIdx.x == 0) {
        float mean = sh_s[0] * (1.f / n);
        float var  = sh_ss[0] * (1.f / n) - mean * mean;
        stats[blockIdx.x] = make_float2(mean, rsqrtf(var + EPS));
    }
}

// ---------------------------------------------------------------------------
// GroupNorm pass 2: normalize + transpose -> hnT[b, p, c] (bf16)
// ---------------------------------------------------------------------------
__global__ __launch_bounds__(256) void gn_transpose_kernel(
    const float* __restrict__ x, const float* __restrict__ scale,
    const float* __restrict__ bias, const float2* __restrict__ stats,
    bf16* __restrict__ hnT)
{
    __shared__ float tile[32][33];
    int b = blockIdx.z, c0 = blockIdx.y * 32, p0 = blockIdx.x * 32;
    int lane = threadIdx.x & 31, r = threadIdx.x >> 5;
    #pragma unroll
    for (int i = 0; i < 4; i++) {
        int cl = r + i * 8, ch = c0 + cl;
        float2 st = stats[b * 32 + (ch >> 4)];
        float a = scale[ch] * st.y;
        float ad = bias[ch] - st.x * a;
        tile[cl][lane] = x[((size_t)b * C_ + ch) * HW + p0 + lane] * a + ad;
    }
    __syncthreads();
    #pragma unroll
    for (int i = 0; i < 4; i++) {
        int pl = r + i * 8;
        hnT[((size_t)b * HW + p0 + pl) * C_ + c0 + lane] = __float2bfloat16(tile[lane][pl]);
    }
}

// ---------------------------------------------------------------------------
// bf16 mma.sync GEMM: D[m,n] = alpha * sum_k A[m,k]*B[n,k]  (+bias) (+R)
// CTA tile 128x128x32, 128 threads (4 warps, 2x2), warp tile 64x64.
// 5-stage cp.async ring + register fragment double buffering.
// ---------------------------------------------------------------------------
#define BM 128
#define BN 128
#define BKB 32                         // k per tile (bf16 elems)
#define ROWB 80                        // bytes per smem row (64 data + 16 pad)
#define STAGE_B (BM * ROWB)            // 10240 bytes per operand stage
#define NSTAGE 5
#define GEMM_SMEM (2 * NSTAGE * STAGE_B)   // 102400 bytes

template<bool BIAS_M, bool BIAS_N, bool RES, bool OUTBF>
__global__ __launch_bounds__(128, 2) void gemm_bf(
    const bf16* __restrict__ A, const bf16* __restrict__ Bm, void* __restrict__ Cp,
    const float* __restrict__ bias, const float* __restrict__ R,
    int M, int N, int K, size_t sA, size_t sB, size_t sC, size_t sR, float alpha)
{
    extern __shared__ char smem[];
    uint32_t su = smem_u32(smem);
    const uint32_t BOFF = NSTAGE * STAGE_B;

    int tid = threadIdx.x, lane = tid & 31, wid = tid >> 5;
    int bz = blockIdx.z;
    A += sA * bz; Bm += sB * bz;
    if (RES) R += sR * bz;
    int m0 = blockIdx.y * BM, n0 = blockIdx.x * BN;

    int wm = (wid & 1) * 64;           // warp m-offset (64-wide)
    int wn = (wid >> 1) * 64;          // warp n-offset (64-wide)
    int g = lane >> 2, c = lane & 3;

    // ldmatrix per-lane offsets (bytes, within a stage)
    int a_row = (lane & 7) + ((lane >> 3) & 1) * 8;
    int a_kh  = lane >> 4;
    uint32_t aoff = (uint32_t)((wm + a_row) * ROWB + a_kh * 16);
    int b_row = (lane & 7) + ((lane >> 4) & 1) * 8;
    int b_kh  = (lane >> 3) & 1;
    uint32_t boffb = (uint32_t)((wn + b_row) * ROWB + b_kh * 16);

    float acc[4][8][4];
    #pragma unroll
    for (int mt = 0; mt < 4; mt++)
        #pragma unroll
        for (int nt = 0; nt < 8; nt++)
            #pragma unroll
            for (int r_ = 0; r_ < 4; r_++) acc[mt][nt][r_] = 0.f;

    int lrow = tid >> 2, lch = tid & 3;
    auto load_tile = [&](int kt, int st) {
        const bf16* Ag = A  + (size_t)m0 * K + kt * BKB;
        const bf16* Bg = Bm + (size_t)n0 * K + kt * BKB;
        uint32_t so = su + (uint32_t)st * STAGE_B;
        #pragma unroll
        for (int i = 0; i < 4; i++) {
            int row = lrow + i * 32;
            uint32_t off = (uint32_t)(row * ROWB + lch * 16);
            cp16(so + off,        Ag + (size_t)row * K + lch * 8);
            cp16(so + BOFF + off, Bg + (size_t)row * K + lch * 8);
        }
        asm volatile("cp.async.commit_group;" ::: "memory");
    };

    // fragment double buffers
    uint32_t af[2][4][4], bfr[2][4][4];
    auto ldsm_slab = [&](int st, int sl, int buf) {
        uint32_t abase = su + (uint32_t)st * STAGE_B;
        uint32_t bbase = abase + BOFF;
        uint32_t ko = (uint32_t)sl * 32;
        #pragma unroll
        for (int mt = 0; mt < 4; mt++)
            ldsm4(af[buf][mt], abase + aoff + mt * (16 * ROWB) + ko);
        #pragma unroll
        for (int pr = 0; pr < 4; pr++)
            ldsm4(bfr[buf][pr], bbase + boffb + pr * (16 * ROWB) + ko);
    };
    auto mma_slab = [&](int buf) {
        #pragma unroll
        for (int pr = 0; pr < 4; pr++)
            #pragma unroll
            for (int mt = 0; mt < 4; mt++) {
                mma16(acc[mt][pr * 2 + 0], af[buf][mt], bfr[buf][pr][0], bfr[buf][pr][1]);
                mma16(acc[mt][pr * 2 + 1], af[buf][mt], bfr[buf][pr][2], bfr[buf][pr][3]);
            }
    };

    // prologue: 4 tiles in flight
    load_tile(0, 0); load_tile(1, 1); load_tile(2, 2); load_tile(3, 3);
    asm volatile("cp.async.wait_group 3;" ::: "memory");
    __syncthreads();
    ldsm_slab(0, 0, 0);                      // tile 0, slab 0 -> buf 0

    const int KT = K / BKB;
    for (int kt = 0; kt < KT; kt++) {
        int cur = kt % NSTAGE;
        ldsm_slab(cur, 1, 1);                // slab 1 -> buf 1 (hidden by mma below)
        mma_slab(0);                         // slab 0
        if (kt + 4 < KT) load_tile(kt + 4, (kt + 4) % NSTAGE);
        if (kt + 1 < KT) {
            // wait until stage kt+1 has landed for every thread
            if (kt + 4 < KT)      asm volatile("cp.async.wait_group 3;" ::: "memory");
            else if (kt + 3 < KT) asm volatile("cp.async.wait_group 2;" ::: "memory");
            else if (kt + 2 < KT) asm volatile("cp.async.wait_group 1;" ::: "memory");
            else                  asm volatile("cp.async.wait_group 0;" ::: "memory");
            __syncthreads();
            ldsm_slab((kt + 1) % NSTAGE, 0, 0);   // next tile slab 0
        }
        mma_slab(1);                         // slab 1
    }

    // epilogue
    #pragma unroll
    for (int mt = 0; mt < 4; mt++) {
        #pragma unroll
        for (int half = 0; half < 2; half++) {
            int m = m0 + wm + mt * 16 + g + half * 8;
            float bm = BIAS_M ? bias[m] : 0.f;
            #pragma unroll
            for (int nt = 0; nt < 8; nt++) {
                int n = n0 + wn + nt * 8 + c * 2;
                float v0 = acc[mt][nt][half * 2 + 0] * alpha + bm;
                float v1 = acc[mt][nt][half * 2 + 1] * alpha + bm;
                if (BIAS_N) { v0 += bias[n]; v1 += bias[n + 1]; }
                size_t off = (size_t)m * N + n;
                if (RES) { v0 += R[off]; v1 += R[off + 1]; }
                if (OUTBF) {
                    *(__nv_bfloat162*)((bf16*)Cp + sC * bz + off) = __floats2bfloat162_rn(v0, v1);
                } else {
                    *(float2*)((float*)Cp + sC * bz + off) = make_float2(v0, v1);
                }
            }
        }
    }
}

// ---------------------------------------------------------------------------
// Row softmax: warp per row, shuffle reductions, fp32 in -> bf16 out
// ---------------------------------------------------------------------------
__global__ __launch_bounds__(256) void softmax_kernel(const float* __restrict__ attn,
                                                      bf16* __restrict__ probs)
{
    int warp = threadIdx.x >> 5, lane = threadIdx.x & 31;
    size_t row = (size_t)blockIdx.x * 8 + warp;
    const float4* p4 = (const float4*)(attn + row * HW);

    float4 v[8];
    #pragma unroll
    for (int i = 0; i < 8; i++) v[i] = p4[lane + i * 32];

    float m = -1e30f;
    #pragma unroll
    for (int i = 0; i < 8; i++)
        m = fmaxf(m, fmaxf(fmaxf(v[i].x, v[i].y), fmaxf(v[i].z, v[i].w)));
    #pragma unroll
    for (int o = 16; o > 0; o >>= 1) m = fmaxf(m, __shfl_xor_sync(0xFFFFFFFFu, m, o));

    float s = 0.f;
    #pragma unroll
    for (int i = 0; i < 8; i++) {
        v[i].x = __expf(v[i].x - m); v[i].y = __expf(v[i].y - m);
        v[i].z = __expf(v[i].z - m); v[i].w = __expf(v[i].w - m);
        s += v[i].x + v[i].y + v[i].z + v[i].w;
    }
    #pragma unroll
    for (int o = 16; o > 0; o >>= 1) s += __shfl_xor_sync(0xFFFFFFFFu, s, o);
    float inv = 1.f / s;

    bf16* op = probs + row * HW;
    #pragma unroll
    for (int i = 0; i < 8; i++) {
        __nv_bfloat162* o2 = (__nv_bfloat162*)(op + (lane + i * 32) * 4);
        o2[0] = __floats2bfloat162_rn(v[i].x * inv, v[i].y * inv);
        o2[1] = __floats2bfloat162_rn(v[i].z * inv, v[i].w * inv);
    }
}

// ---------------------------------------------------------------------------
extern "C" void kernel_launch(void* const* d_in, const int* in_sizes, int n_in,
                              void* d_out, int out_size)
{
    const float* x  = (const float*)d_in[0];
    const float* gs = (const float*)d_in[1];
    const float* gb = (const float*)d_in[2];
    const float* wq = (const float*)d_in[3];
    const float* bq = (const float*)d_in[4];
    const float* wk = (const float*)d_in[5];
    const float* bk = (const float*)d_in[6];
    const float* wv = (const float*)d_in[7];
    const float* bv = (const float*)d_in[8];
    const float* wp = (const float*)d_in[9];
    const float* bp = (const float*)d_in[10];
    float* out = (float*)d_out;

    bf16 *hnT, *qT, *kT, *v, *oT, *probs, *wb; float* attn; float2* stats;
    cudaGetSymbolAddress((void**)&hnT,   g_hnT);
    cudaGetSymbolAddress((void**)&qT,    g_qT);
    cudaGetSymbolAddress((void**)&kT,    g_kT);
    cudaGetSymbolAddress((void**)&v,     g_v);
    cudaGetSymbolAddress((void**)&oT,    g_oT);
    cudaGetSymbolAddress((void**)&attn,  g_attn);
    cudaGetSymbolAddress((void**)&probs, g_probs);
    cudaGetSymbolAddress((void**)&wb,    g_w);
    cudaGetSymbolAddress((void**)&stats, g_stats);
    bf16 *wqb = wb, *wkb = wb + C_ * C_, *wvb = wb + 2 * C_ * C_, *wpb = wb + 3 * C_ * C_;

    cudaFuncSetAttribute(gemm_bf<false, true,  false, true >, cudaFuncAttributeMaxDynamicSharedMemorySize, GEMM_SMEM);
    cudaFuncSetAttribute(gemm_bf<true,  false, false, true >, cudaFuncAttributeMaxDynamicSharedMemorySize, GEMM_SMEM);
    cudaFuncSetAttribute(gemm_bf<false, false, false, false>, cudaFuncAttributeMaxDynamicSharedMemorySize, GEMM_SMEM);
    cudaFuncSetAttribute(gemm_bf<false, false, false, true >, cudaFuncAttributeMaxDynamicSharedMemorySize, GEMM_SMEM);
    cudaFuncSetAttribute(gemm_bf<true,  false, true,  false>, cudaFuncAttributeMaxDynamicSharedMemorySize, GEMM_SMEM);

    const size_t sCH = (size_t)C_ * HW;
    const size_t sAA = (size_t)HW * HW;
    const float  scl = 1.f / sqrtf((float)C_);

    // 0) weights -> bf16 (one launch)
    cvt4_kernel<<<dim3(C_ * C_ / 1024, 4), 256>>>(wq, wk, wv, wp, wb);

    // 1) GroupNorm stats + normalize/transpose -> hnT (bf16)
    gn_stats_kernel<<<B_ * 32, 256>>>(x, stats);
    gn_transpose_kernel<<<dim3(HW / 32, C_ / 32, B_), 256>>>(x, gs, gb, stats, hnT);

    // 2) QT/KT[p,o] = hnT @ w^T + b        (M=1024, N=512, K=512) -> bf16
    {
        dim3 g(512 / BN, 1024 / BM, B_);
        gemm_bf<false, true, false, true><<<g, 128, GEMM_SMEM>>>(
            hnT, wqb, qT, bq, nullptr, 1024, 512, 512, sCH, 0, sCH, 0, 1.f);
        gemm_bf<false, true, false, true><<<g, 128, GEMM_SMEM>>>(
            hnT, wkb, kT, bk, nullptr, 1024, 512, 512, sCH, 0, sCH, 0, 1.f);
    }
    // 3) V[co,p] = wv @ hnT^T + bv         (M=512, N=1024, K=512) -> bf16
    {
        dim3 g(1024 / BN, 512 / BM, B_);
        gemm_bf<true, false, false, true><<<g, 128, GEMM_SMEM>>>(
            wvb, hnT, v, bv, nullptr, 512, 1024, 512, 0, sCH, sCH, 0, 1.f);
    }
    // 4) S = scl * QT @ KT^T               (M=1024, N=1024, K=512) -> fp32
    {
        dim3 g(1024 / BN, 1024 / BM, B_);
        gemm_bf<false, false, false, false><<<g, 128, GEMM_SMEM>>>(
            qT, kT, attn, nullptr, nullptr, 1024, 1024, 512, sCH, sCH, sAA, 0, scl);
    }
    // 5) softmax -> bf16 probs (warp per row)
    softmax_kernel<<<B_ * HW / 8, 256>>>(attn, probs);

    // 6) OT[i,co] = probs @ V^T            (M=1024, N=512, K=1024) -> bf16
    {
        dim3 g(512 / BN, 1024 / BM, B_);
        gemm_bf<false, false, false, true><<<g, 128, GEMM_SMEM>>>(
            probs, v, oT, nullptr, nullptr, 1024, 512, 1024, sAA, sCH, sCH, 0, 1.f);
    }
    // 7) out[co,p] = wp @ OT^T + bp + x    (M=512, N=1024, K=512) -> fp32 + residual
    {
        dim3 g(1024 / BN, 512 / BM, B_);
        gemm_bf<true, false, true, false><<<g, 128, GEMM_SMEM>>>(
            wpb, oT, out, bp, x, 512, 1024, 512, 0, sCH, sCH, sCH, 1.f);
    }
}